// round 12
// baseline (speedup 1.0000x reference)
#include <cuda_runtime.h>
#include <cuda_fp16.h>
#include <cstdint>

// ---------------------------------------------------------------------------
// SelfAttention B=4, S=2048, D=1024 fp32 — mma.sync.m16n8k16.f16 pipeline.
// R11 -> R12: QKV split into QK-proj (default stream) + V-proj (side stream,
// capture-fork via events). V-proj backfills the wave-quantization drains of
// QK-proj and scores. GEMM mainloop identical to R11 (303.1us baseline).
// ---------------------------------------------------------------------------

#define BATCH 4
#define SEQ   2048
#define DIM   1024
#define BS_   (BATCH * SEQ)

__device__ __half g_xh  [BS_ * DIM];                 // rounded x (fp16)
__device__ __half g_wqkv[3 * DIM * DIM];             // rounded [Wq;Wk;Wv]
__device__ float  g_bias[3 * DIM];                   // [bq;bk;bv] fp32
__device__ __half g_q [BS_ * DIM];                   // Q fp16
__device__ __half g_k [BS_ * DIM];                   // K fp16
__device__ __half g_vt[BS_ * DIM];                   // V^T fp16 [B][D][S]
__device__ __half g_p [(size_t)BATCH * SEQ * SEQ];   // P' = exp(s/32) fp16
__device__ float  g_rowsum[BS_];                     // softmax denominators

// ------------------------------ helpers -----------------------------------
__device__ __forceinline__ uint32_t smem_u32(const void* p) {
    uint32_t a;
    asm("{ .reg .u64 t; cvta.to.shared.u64 t, %1; cvt.u32.u64 %0, t; }"
        : "=r"(a) : "l"(p));
    return a;
}
__device__ __forceinline__ void cp16(uint32_t dst, const void* src) {
    asm volatile("cp.async.cg.shared.global [%0], [%1], 16;\n"
                 :: "r"(dst), "l"(src));
}
__device__ __forceinline__ void ldsm_x4(uint32_t* r, uint32_t a) {
    asm volatile("ldmatrix.sync.aligned.m8n8.x4.shared.b16 {%0,%1,%2,%3}, [%4];"
                 : "=r"(r[0]), "=r"(r[1]), "=r"(r[2]), "=r"(r[3]) : "r"(a));
}
__device__ __forceinline__ void mma_f16(float* c, const uint32_t* a, const uint32_t* b) {
    asm volatile(
        "mma.sync.aligned.m16n8k16.row.col.f32.f16.f16.f32 "
        "{%0,%1,%2,%3}, {%4,%5,%6,%7}, {%8,%9}, {%0,%1,%2,%3};"
        : "+f"(c[0]), "+f"(c[1]), "+f"(c[2]), "+f"(c[3])
        : "r"(a[0]), "r"(a[1]), "r"(a[2]), "r"(a[3]), "r"(b[0]), "r"(b[1]));
}
#define SW128(o) ((o) ^ (((o) >> 3) & 0x70))

// ------------------------------ fused prepass ------------------------------
#define N4_X   (BS_ * DIM / 4)
#define N4_W   (3 * DIM * DIM / 4)
#define N4_W1  (DIM * DIM / 4)
#define N4_B1  (DIM / 4)
#define N4_RS  (BS_ / 4)
#define N4_ALL (N4_X + N4_W + 3 * N4_B1 + N4_RS)  // 2886400 = 11275 * 256

__global__ void __launch_bounds__(256) prepass_kernel(
    const float4* __restrict__ x,
    const float4* __restrict__ Wq, const float4* __restrict__ Wk,
    const float4* __restrict__ Wv,
    const float4* __restrict__ bq, const float4* __restrict__ bk,
    const float4* __restrict__ bv)
{
    int i = blockIdx.x * blockDim.x + threadIdx.x;
    if (i < N4_X) {
        float4 v = x[i];
        ((__half2*)g_xh)[2 * i]     = __floats2half2_rn(v.x, v.y);
        ((__half2*)g_xh)[2 * i + 1] = __floats2half2_rn(v.z, v.w);
    } else if (i < N4_X + N4_W) {
        int j = i - N4_X;
        float4 v = (j < N4_W1) ? Wq[j]
                 : (j < 2 * N4_W1) ? Wk[j - N4_W1] : Wv[j - 2 * N4_W1];
        ((__half2*)g_wqkv)[2 * j]     = __floats2half2_rn(v.x, v.y);
        ((__half2*)g_wqkv)[2 * j + 1] = __floats2half2_rn(v.z, v.w);
    } else if (i < N4_X + N4_W + 3 * N4_B1) {
        int j = i - N4_X - N4_W;
        float4 v = (j < N4_B1) ? bq[j]
                 : (j < 2 * N4_B1) ? bk[j - N4_B1] : bv[j - 2 * N4_B1];
        ((float4*)g_bias)[j] = v;
    } else {
        int j = i - N4_X - N4_W - 3 * N4_B1;
        ((float4*)g_rowsum)[j] = make_float4(0.f, 0.f, 0.f, 0.f);
    }
}

// ------------------------------ FP16 GEMM ----------------------------------
// C[M,N] = A[M,K] @ B^T  (A [M,K], B [N,K], both fp16 K-major)
// CTA 128(M) x 128(N), BK=64, 3-stage cp.async pipeline, 2 CTAs/SM.
// 128 threads: warp grid 2(m) x 2(n), warp tile 64x64, mma m16n8k16.
// EPI_NORM : fp32 out scaled by 1/g_rowsum[row]  (PV)
// EPI_EXP_H: fp16 out = exp(acc*scale), accumulates g_rowsum  (scores)
// EPI_QK   : +bias, round fp16, route to g_q / g_k  (N=2048)
// EPI_V    : +bias (offset 2048), round fp16, transposed store to g_vt
enum { EPI_NORM = 0, EPI_EXP_H = 1, EPI_QK = 2, EPI_V = 3 };

#define A_TILE 16384
#define B_TILE 16384
#define STAGE  (A_TILE + B_TILE)
#define NSTAGE 3
#define GEMM_SMEM (NSTAGE * STAGE)   // 96 KB

template <int EPI>
__global__ void __launch_bounds__(128, 2) gemm_f16(
    const __half* __restrict__ A, const __half* __restrict__ B,
    float* __restrict__ C,
    int K, int N, long long sA, long long sB, long long sC, float scale)
{
    extern __shared__ __align__(128) char smem[];
    const uint32_t base = smem_u32(smem);

    const int tid = threadIdx.x;
    const int wid = tid >> 5, lid = tid & 31;
    const int wm = wid & 1;
    const int wn = wid >> 1;

    A += blockIdx.z * sA;
    B += blockIdx.z * sB;
    float*  Cf = C + ((EPI == EPI_NORM) ? blockIdx.z * sC : 0);
    __half* Ch = (EPI == EPI_EXP_H) ? ((__half*)C + blockIdx.z * sC) : nullptr;
    const int gz = blockIdx.z * SEQ;   // rowsum batch offset

    const long long m0 = (long long)blockIdx.y * 128;
    const int       n0 = blockIdx.x * 128;

    const __half* Abase = A + m0 * (long long)K;
    const __half* Bbase = B + (long long)n0 * K;

    // A x4 lane addressing
    const int a_row_l = ((lid >> 3) & 1) * 8 + (lid & 7);
    const int a_hi    = lid >> 4;
    uint32_t a_rb[4]; int a_rx[4];
#pragma unroll
    for (int mt = 0; mt < 4; mt++) {
        int fr = wm * 64 + mt * 16 + a_row_l;
        a_rb[mt] = fr * 128; a_rx[mt] = fr & 7;
    }
    // B x4 lane addressing
    const int b4_row = ((lid >> 4) << 3) + (lid & 7);
    const int b4_hi  = (lid >> 3) & 1;
    uint32_t b_rb[4]; int b_rx[4];
#pragma unroll
    for (int nt2 = 0; nt2 < 4; nt2++) {
        int fr = wn * 64 + nt2 * 16 + b4_row;
        b_rb[nt2] = fr * 128; b_rx[nt2] = fr & 7;
    }

    // per-thread loader coords
    const int l_r = tid >> 3;          // 0..15 base row within 16-row group
    const int l_c = tid & 7;           // 16B chunk within 128B row

    auto load_tile = [&](int j, int b) {
        const uint32_t sa = base + b * STAGE;
        const uint32_t sb = sa + A_TILE;
        const __half* At = Abase + (long long)j * 64;
        const __half* Bt = Bbase + (long long)j * 64;
#pragma unroll
        for (int t = 0; t < 8; t++) {
            int r = l_r + t * 16;
            cp16(sa + SW128(r * 128 + l_c * 16), At + (long long)r * K + l_c * 8);
        }
#pragma unroll
        for (int t = 0; t < 8; t++) {
            int r = l_r + t * 16;
            cp16(sb + SW128(r * 128 + l_c * 16), Bt + (long long)r * K + l_c * 8);
        }
        asm volatile("cp.async.commit_group;" ::: "memory");
    };

    float acc[4][8][4];
#pragma unroll
    for (int mt = 0; mt < 4; mt++)
#pragma unroll
        for (int nt = 0; nt < 8; nt++)
#pragma unroll
            for (int r = 0; r < 4; r++) acc[mt][nt][r] = 0.f;

    const int T = K >> 6;
    load_tile(0, 0);
    load_tile(1, 1);

    int cb = 0;           // buffer being computed this iter
    int pb = 2;           // buffer being prefetched this iter
    for (int i = 0; i < T; i++) {
        const int rem = T - 1 - i;
        if (rem >= 1) asm volatile("cp.async.wait_group 1;" ::: "memory");
        else          asm volatile("cp.async.wait_group 0;" ::: "memory");
        __syncthreads();

        const bool pf = (i + 2 < T);
        const uint32_t sa = base + cb * STAGE;
        const uint32_t sb = sa + A_TILE;
        const uint32_t pa = base + pb * STAGE;
        const uint32_t pbb = pa + A_TILE;
        const __half* At = Abase + (long long)(i + 2) * 64;
        const __half* Bt = Bbase + (long long)(i + 2) * 64;

#pragma unroll
        for (int s = 0; s < 4; s++) {
            uint32_t af[4][4], bf[8][2];
#pragma unroll
            for (int mt = 0; mt < 4; mt++)
                ldsm_x4(af[mt], sa + a_rb[mt] + ((((s << 1) | a_hi) ^ a_rx[mt]) << 4));
#pragma unroll
            for (int nt2 = 0; nt2 < 4; nt2++) {
                uint32_t r[4];
                ldsm_x4(r, sb + b_rb[nt2] + ((((s << 1) | b4_hi) ^ b_rx[nt2]) << 4));
                bf[2 * nt2][0]     = r[0]; bf[2 * nt2][1]     = r[1];
                bf[2 * nt2 + 1][0] = r[2]; bf[2 * nt2 + 1][1] = r[3];
            }
            // interleaved prefetch: 4 cp.async per s-step
            if (pf) {
                int r0 = l_r + (2 * s) * 16, r1 = l_r + (2 * s + 1) * 16;
                cp16(pa  + SW128(r0 * 128 + l_c * 16), At + (long long)r0 * K + l_c * 8);
                cp16(pa  + SW128(r1 * 128 + l_c * 16), At + (long long)r1 * K + l_c * 8);
                cp16(pbb + SW128(r0 * 128 + l_c * 16), Bt + (long long)r0 * K + l_c * 8);
                cp16(pbb + SW128(r1 * 128 + l_c * 16), Bt + (long long)r1 * K + l_c * 8);
            }
#pragma unroll
            for (int mt = 0; mt < 4; mt++)
#pragma unroll
                for (int nt = 0; nt < 8; nt++)
                    mma_f16(acc[mt][nt], af[mt], bf[nt]);
        }
        if (pf) asm volatile("cp.async.commit_group;" ::: "memory");

        cb = (cb == NSTAGE - 1) ? 0 : cb + 1;
        pb = (pb == NSTAGE - 1) ? 0 : pb + 1;
    }

    // ------------------------------ epilogue -------------------------------
    const int g = lid >> 2, t = lid & 3;

    float inv[8];                       // EPI_NORM row scales (hoisted loads)
    if (EPI == EPI_NORM) {
#pragma unroll
        for (int mt = 0; mt < 4; mt++) {
            const long long r0 = m0 + wm * 64 + mt * 16 + g;
            inv[2 * mt]     = 1.0f / g_rowsum[gz + r0];
            inv[2 * mt + 1] = 1.0f / g_rowsum[gz + r0 + 8];
        }
    }

#pragma unroll
    for (int mt = 0; mt < 4; mt++) {
        const long long r0 = m0 + wm * 64 + mt * 16 + g;
        float rs0 = 0.f, rs1 = 0.f;     // EPI_EXP_H row-sum partials
#pragma unroll
        for (int nt = 0; nt < 8; nt++) {
            const int col = n0 + wn * 64 + nt * 8 + t * 2;
            float v0 = acc[mt][nt][0], v1 = acc[mt][nt][1];
            float v2 = acc[mt][nt][2], v3 = acc[mt][nt][3];

            if (EPI == EPI_NORM) {
                const float i0 = inv[2 * mt], i1 = inv[2 * mt + 1];
                *(float2*)(Cf + r0 * N + col)       = make_float2(v0 * i0, v1 * i0);
                *(float2*)(Cf + (r0 + 8) * N + col) = make_float2(v2 * i1, v3 * i1);
            } else if (EPI == EPI_EXP_H) {
                float e0 = __expf(v0 * scale), e1 = __expf(v1 * scale);
                float e2 = __expf(v2 * scale), e3 = __expf(v3 * scale);
                *(__half2*)(Ch + r0 * N + col)       = __floats2half2_rn(e0, e1);
                *(__half2*)(Ch + (r0 + 8) * N + col) = __floats2half2_rn(e2, e3);
                rs0 += e0 + e1;
                rs1 += e2 + e3;
            } else if (EPI == EPI_QK) {
                const float2 bv = *(const float2*)(g_bias + col);
                const __half2 h01 = __floats2half2_rn(v0 + bv.x, v1 + bv.y);
                const __half2 h23 = __floats2half2_rn(v2 + bv.x, v3 + bv.y);
                const int mat = col >> 10;           // 0=q, 1=k
                const int cl  = col & 1023;
                if (mat == 0) {
                    *(__half2*)(g_q + r0 * DIM + cl)       = h01;
                    *(__half2*)(g_q + (r0 + 8) * DIM + cl) = h23;
                } else {
                    *(__half2*)(g_k + r0 * DIM + cl)       = h01;
                    *(__half2*)(g_k + (r0 + 8) * DIM + cl) = h23;
                }
            } else {  // EPI_V: transposed store, bias offset 2048
                const float2 bv = *(const float2*)(g_bias + 2048 + col);
                const __half2 h01 = __floats2half2_rn(v0 + bv.x, v1 + bv.y);
                const __half2 h23 = __floats2half2_rn(v2 + bv.x, v3 + bv.y);
                const long long bofs = (r0 >> 11) * (long long)DIM * SEQ;
                const long long sq0 = r0 & 2047, sq1 = (r0 + 8) & 2047;
                g_vt[bofs + (long long)(col    ) * SEQ + sq0] = __low2half(h01);
                g_vt[bofs + (long long)(col + 1) * SEQ + sq0] = __high2half(h01);
                g_vt[bofs + (long long)(col    ) * SEQ + sq1] = __low2half(h23);
                g_vt[bofs + (long long)(col + 1) * SEQ + sq1] = __high2half(h23);
            }
        }
        if (EPI == EPI_EXP_H) {
            rs0 += __shfl_xor_sync(0xffffffffu, rs0, 1);
            rs0 += __shfl_xor_sync(0xffffffffu, rs0, 2);
            rs1 += __shfl_xor_sync(0xffffffffu, rs1, 1);
            rs1 += __shfl_xor_sync(0xffffffffu, rs1, 2);
            if (t == 0) {
                atomicAdd(&g_rowsum[gz + r0],     rs0);
                atomicAdd(&g_rowsum[gz + r0 + 8], rs1);
            }
        }
    }
}

// ------------------------------ launch -------------------------------------
extern "C" void kernel_launch(void* const* d_in, const int* in_sizes, int n_in,
                              void* d_out, int out_size)
{
    (void)in_sizes; (void)n_in; (void)out_size;
    const float* x  = (const float*)d_in[0];
    const float* Wq = (const float*)d_in[1];
    const float* bq = (const float*)d_in[2];
    const float* Wk = (const float*)d_in[3];
    const float* bk = (const float*)d_in[4];
    const float* Wv = (const float*)d_in[5];
    const float* bv = (const float*)d_in[6];
    float* out = (float*)d_out;

    __half *xh, *wqkv, *q, *k, *vt, *p;
    cudaGetSymbolAddress((void**)&xh,   g_xh);
    cudaGetSymbolAddress((void**)&wqkv, g_wqkv);
    cudaGetSymbolAddress((void**)&q,    g_q);
    cudaGetSymbolAddress((void**)&k,    g_k);
    cudaGetSymbolAddress((void**)&vt,   g_vt);
    cudaGetSymbolAddress((void**)&p,    g_p);

    cudaFuncSetAttribute(gemm_f16<EPI_QK>,    cudaFuncAttributeMaxDynamicSharedMemorySize, GEMM_SMEM);
    cudaFuncSetAttribute(gemm_f16<EPI_V>,     cudaFuncAttributeMaxDynamicSharedMemorySize, GEMM_SMEM);
    cudaFuncSetAttribute(gemm_f16<EPI_EXP_H>, cudaFuncAttributeMaxDynamicSharedMemorySize, GEMM_SMEM);
    cudaFuncSetAttribute(gemm_f16<EPI_NORM>,  cudaFuncAttributeMaxDynamicSharedMemorySize, GEMM_SMEM);

    // side stream + events for capture-fork (created per call; leaked — only
    // ~3 invocations total, no device memory involved)
    cudaStream_t sB;
    cudaStreamCreateWithFlags(&sB, cudaStreamNonBlocking);
    cudaEvent_t ev0, evV;
    cudaEventCreateWithFlags(&ev0, cudaEventDisableTiming);
    cudaEventCreateWithFlags(&evV, cudaEventDisableTiming);

    // 1) prepass (default stream)
    prepass_kernel<<<N4_ALL / 256, 256>>>(
        (const float4*)x, (const float4*)Wq, (const float4*)Wk, (const float4*)Wv,
        (const float4*)bq, (const float4*)bk, (const float4*)bv);

    // fork: side stream waits for prepass
    cudaEventRecord(ev0, 0);
    cudaStreamWaitEvent(sB, ev0, 0);

    // 1b) V projection on side stream: [8192,1024] @ Wv^T -> g_vt (transposed)
    {
        dim3 grid(DIM / 128, BS_ / 128, 1);
        gemm_f16<EPI_V><<<grid, 128, GEMM_SMEM, sB>>>(
            xh, wqkv + 2 * DIM * DIM, nullptr, DIM, DIM, 0, 0, 0, 1.0f);
    }
    cudaEventRecord(evV, sB);

    // 2) QK projection (default stream): [8192,1024] @ [2048,1024]^T
    {
        dim3 grid(2 * DIM / 128, BS_ / 128, 1);
        gemm_f16<EPI_QK><<<grid, 128, GEMM_SMEM>>>(
            xh, wqkv, nullptr, DIM, 2 * DIM, 0, 0, 0, 1.0f);
    }

    // 3) P' = exp(QK^T / 32) -> fp16 g_p + row sums (sC in half units)
    {
        dim3 grid(SEQ / 128, SEQ / 128, BATCH);
        gemm_f16<EPI_EXP_H><<<grid, 128, GEMM_SMEM>>>(
            q, k, (float*)p, DIM, SEQ,
            (long long)SEQ * DIM, (long long)SEQ * DIM, (long long)SEQ * SEQ, 0.03125f);
    }

    // join: PV needs V (side stream) + scores/rowsums (default stream)
    cudaStreamWaitEvent(0, evV, 0);

    // 4) out = (P' @ V) / rowsum  (V^T fp16 [DIM,SEQ] K-major), fp32 out
    {
        dim3 grid(DIM / 128, SEQ / 128, BATCH);
        gemm_f16<EPI_NORM><<<grid, 128, GEMM_SMEM>>>(
            p, vt, out, SEQ, DIM,
            (long long)SEQ * SEQ, (long long)DIM * SEQ, (long long)SEQ * DIM, 1.0f);
    }
}

// round 13
// speedup vs baseline: 1.0090x; 1.0090x over previous
#include <cuda_runtime.h>
#include <cuda_fp16.h>
#include <cstdint>

// ---------------------------------------------------------------------------
// SelfAttention B=4, S=2048, D=1024 fp32 — mma.sync.m16n8k16.f16 pipeline.
// R12 -> R13: revert stream-fork (neutral-negative); back to serial fused
// QKV. One change vs R11: A/B ldmatrix issue interleaved (a0,b0,a1,b1,...)
// so the first MMA's operands arrive one LDSM-latency earlier per s-step.
// 128x128 tiles, 128 threads, 3-stage cp.async (interleaved prefetch),
// 2 CTAs/SM. Softmax fused into GEMM epilogues.
// ---------------------------------------------------------------------------

#define BATCH 4
#define SEQ   2048
#define DIM   1024
#define BS_   (BATCH * SEQ)

__device__ __half g_xh  [BS_ * DIM];                 // rounded x (fp16)
__device__ __half g_wqkv[3 * DIM * DIM];             // rounded [Wq;Wk;Wv]
__device__ float  g_bias[3 * DIM];                   // [bq;bk;bv] fp32
__device__ __half g_q [BS_ * DIM];                   // Q fp16
__device__ __half g_k [BS_ * DIM];                   // K fp16
__device__ __half g_vt[BS_ * DIM];                   // V^T fp16 [B][D][S]
__device__ __half g_p [(size_t)BATCH * SEQ * SEQ];   // P' = exp(s/32) fp16
__device__ float  g_rowsum[BS_];                     // softmax denominators

// ------------------------------ helpers -----------------------------------
__device__ __forceinline__ uint32_t smem_u32(const void* p) {
    uint32_t a;
    asm("{ .reg .u64 t; cvta.to.shared.u64 t, %1; cvt.u32.u64 %0, t; }"
        : "=r"(a) : "l"(p));
    return a;
}
__device__ __forceinline__ void cp16(uint32_t dst, const void* src) {
    asm volatile("cp.async.cg.shared.global [%0], [%1], 16;\n"
                 :: "r"(dst), "l"(src));
}
__device__ __forceinline__ void ldsm_x4(uint32_t* r, uint32_t a) {
    asm volatile("ldmatrix.sync.aligned.m8n8.x4.shared.b16 {%0,%1,%2,%3}, [%4];"
                 : "=r"(r[0]), "=r"(r[1]), "=r"(r[2]), "=r"(r[3]) : "r"(a));
}
__device__ __forceinline__ void mma_f16(float* c, const uint32_t* a, const uint32_t* b) {
    asm volatile(
        "mma.sync.aligned.m16n8k16.row.col.f32.f16.f16.f32 "
        "{%0,%1,%2,%3}, {%4,%5,%6,%7}, {%8,%9}, {%0,%1,%2,%3};"
        : "+f"(c[0]), "+f"(c[1]), "+f"(c[2]), "+f"(c[3])
        : "r"(a[0]), "r"(a[1]), "r"(a[2]), "r"(a[3]), "r"(b[0]), "r"(b[1]));
}
#define SW128(o) ((o) ^ (((o) >> 3) & 0x70))

// ------------------------------ fused prepass ------------------------------
#define N4_X   (BS_ * DIM / 4)
#define N4_W   (3 * DIM * DIM / 4)
#define N4_W1  (DIM * DIM / 4)
#define N4_B1  (DIM / 4)
#define N4_RS  (BS_ / 4)
#define N4_ALL (N4_X + N4_W + 3 * N4_B1 + N4_RS)  // 2886400 = 11275 * 256

__global__ void __launch_bounds__(256) prepass_kernel(
    const float4* __restrict__ x,
    const float4* __restrict__ Wq, const float4* __restrict__ Wk,
    const float4* __restrict__ Wv,
    const float4* __restrict__ bq, const float4* __restrict__ bk,
    const float4* __restrict__ bv)
{
    int i = blockIdx.x * blockDim.x + threadIdx.x;
    if (i < N4_X) {
        float4 v = x[i];
        ((__half2*)g_xh)[2 * i]     = __floats2half2_rn(v.x, v.y);
        ((__half2*)g_xh)[2 * i + 1] = __floats2half2_rn(v.z, v.w);
    } else if (i < N4_X + N4_W) {
        int j = i - N4_X;
        float4 v = (j < N4_W1) ? Wq[j]
                 : (j < 2 * N4_W1) ? Wk[j - N4_W1] : Wv[j - 2 * N4_W1];
        ((__half2*)g_wqkv)[2 * j]     = __floats2half2_rn(v.x, v.y);
        ((__half2*)g_wqkv)[2 * j + 1] = __floats2half2_rn(v.z, v.w);
    } else if (i < N4_X + N4_W + 3 * N4_B1) {
        int j = i - N4_X - N4_W;
        float4 v = (j < N4_B1) ? bq[j]
                 : (j < 2 * N4_B1) ? bk[j - N4_B1] : bv[j - 2 * N4_B1];
        ((float4*)g_bias)[j] = v;
    } else {
        int j = i - N4_X - N4_W - 3 * N4_B1;
        ((float4*)g_rowsum)[j] = make_float4(0.f, 0.f, 0.f, 0.f);
    }
}

// ------------------------------ FP16 GEMM ----------------------------------
// C[M,N] = A[M,K] @ B^T  (A [M,K], B [N,K], both fp16 K-major)
// CTA 128(M) x 128(N), BK=64, 3-stage cp.async pipeline, 2 CTAs/SM.
// 128 threads: warp grid 2(m) x 2(n), warp tile 64x64, mma m16n8k16.
// EPI_NORM : fp32 out scaled by 1/g_rowsum[row]  (PV)
// EPI_EXP_H: fp16 out = exp(acc*scale), accumulates g_rowsum  (scores)
// EPI_QKV  : +bias, round fp16, route to g_q / g_k / g_vt
enum { EPI_NORM = 0, EPI_EXP_H = 1, EPI_QKV = 2 };

#define A_TILE 16384
#define B_TILE 16384
#define STAGE  (A_TILE + B_TILE)
#define NSTAGE 3
#define GEMM_SMEM (NSTAGE * STAGE)   // 96 KB

template <int EPI>
__global__ void __launch_bounds__(128, 2) gemm_f16(
    const __half* __restrict__ A, const __half* __restrict__ B,
    float* __restrict__ C,
    int K, int N, long long sA, long long sB, long long sC, float scale)
{
    extern __shared__ __align__(128) char smem[];
    const uint32_t base = smem_u32(smem);

    const int tid = threadIdx.x;
    const int wid = tid >> 5, lid = tid & 31;
    const int wm = wid & 1;
    const int wn = wid >> 1;

    A += blockIdx.z * sA;
    B += blockIdx.z * sB;
    float*  Cf = C + ((EPI == EPI_NORM) ? blockIdx.z * sC : 0);
    __half* Ch = (EPI == EPI_EXP_H) ? ((__half*)C + blockIdx.z * sC) : nullptr;
    const int gz = blockIdx.z * SEQ;   // rowsum batch offset

    const long long m0 = (long long)blockIdx.y * 128;
    const int       n0 = blockIdx.x * 128;

    const __half* Abase = A + m0 * (long long)K;
    const __half* Bbase = B + (long long)n0 * K;

    // A x4 lane addressing
    const int a_row_l = ((lid >> 3) & 1) * 8 + (lid & 7);
    const int a_hi    = lid >> 4;
    uint32_t a_rb[4]; int a_rx[4];
#pragma unroll
    for (int mt = 0; mt < 4; mt++) {
        int fr = wm * 64 + mt * 16 + a_row_l;
        a_rb[mt] = fr * 128; a_rx[mt] = fr & 7;
    }
    // B x4 lane addressing
    const int b4_row = ((lid >> 4) << 3) + (lid & 7);
    const int b4_hi  = (lid >> 3) & 1;
    uint32_t b_rb[4]; int b_rx[4];
#pragma unroll
    for (int nt2 = 0; nt2 < 4; nt2++) {
        int fr = wn * 64 + nt2 * 16 + b4_row;
        b_rb[nt2] = fr * 128; b_rx[nt2] = fr & 7;
    }

    // per-thread loader coords
    const int l_r = tid >> 3;          // 0..15 base row within 16-row group
    const int l_c = tid & 7;           // 16B chunk within 128B row

    auto load_tile = [&](int j, int b) {
        const uint32_t sa = base + b * STAGE;
        const uint32_t sb = sa + A_TILE;
        const __half* At = Abase + (long long)j * 64;
        const __half* Bt = Bbase + (long long)j * 64;
#pragma unroll
        for (int t = 0; t < 8; t++) {
            int r = l_r + t * 16;
            cp16(sa + SW128(r * 128 + l_c * 16), At + (long long)r * K + l_c * 8);
        }
#pragma unroll
        for (int t = 0; t < 8; t++) {
            int r = l_r + t * 16;
            cp16(sb + SW128(r * 128 + l_c * 16), Bt + (long long)r * K + l_c * 8);
        }
        asm volatile("cp.async.commit_group;" ::: "memory");
    };

    float acc[4][8][4];
#pragma unroll
    for (int mt = 0; mt < 4; mt++)
#pragma unroll
        for (int nt = 0; nt < 8; nt++)
#pragma unroll
            for (int r = 0; r < 4; r++) acc[mt][nt][r] = 0.f;

    const int T = K >> 6;
    load_tile(0, 0);
    load_tile(1, 1);

    int cb = 0;           // buffer being computed this iter
    int pb = 2;           // buffer being prefetched this iter
    for (int i = 0; i < T; i++) {
        const int rem = T - 1 - i;
        if (rem >= 1) asm volatile("cp.async.wait_group 1;" ::: "memory");
        else          asm volatile("cp.async.wait_group 0;" ::: "memory");
        __syncthreads();

        const bool pf = (i + 2 < T);
        const uint32_t sa = base + cb * STAGE;
        const uint32_t sb = sa + A_TILE;
        const uint32_t pa = base + pb * STAGE;
        const uint32_t pbb = pa + A_TILE;
        const __half* At = Abase + (long long)(i + 2) * 64;
        const __half* Bt = Bbase + (long long)(i + 2) * 64;

#pragma unroll
        for (int s = 0; s < 4; s++) {
            uint32_t af[4][4], bf[8][2];
            // interleaved A/B ldmatrix issue: first MMA's operands (af[0],
            // bf[0..1]) come from the first two LDSMs instead of #1 and #5.
#pragma unroll
            for (int q = 0; q < 4; q++) {
                ldsm_x4(af[q], sa + a_rb[q] + ((((s << 1) | a_hi) ^ a_rx[q]) << 4));
                uint32_t r[4];
                ldsm_x4(r, sb + b_rb[q] + ((((s << 1) | b4_hi) ^ b_rx[q]) << 4));
                bf[2 * q][0]     = r[0]; bf[2 * q][1]     = r[1];
                bf[2 * q + 1][0] = r[2]; bf[2 * q + 1][1] = r[3];
            }
            // interleaved prefetch: 4 cp.async per s-step
            if (pf) {
                int r0 = l_r + (2 * s) * 16, r1 = l_r + (2 * s + 1) * 16;
                cp16(pa  + SW128(r0 * 128 + l_c * 16), At + (long long)r0 * K + l_c * 8);
                cp16(pa  + SW128(r1 * 128 + l_c * 16), At + (long long)r1 * K + l_c * 8);
                cp16(pbb + SW128(r0 * 128 + l_c * 16), Bt + (long long)r0 * K + l_c * 8);
                cp16(pbb + SW128(r1 * 128 + l_c * 16), Bt + (long long)r1 * K + l_c * 8);
            }
#pragma unroll
            for (int mt = 0; mt < 4; mt++)
#pragma unroll
                for (int nt = 0; nt < 8; nt++)
                    mma_f16(acc[mt][nt], af[mt], bf[nt]);
        }
        if (pf) asm volatile("cp.async.commit_group;" ::: "memory");

        cb = (cb == NSTAGE - 1) ? 0 : cb + 1;
        pb = (pb == NSTAGE - 1) ? 0 : pb + 1;
    }

    // ------------------------------ epilogue -------------------------------
    const int g = lid >> 2, t = lid & 3;

    float inv[8];                       // EPI_NORM row scales (hoisted loads)
    if (EPI == EPI_NORM) {
#pragma unroll
        for (int mt = 0; mt < 4; mt++) {
            const long long r0 = m0 + wm * 64 + mt * 16 + g;
            inv[2 * mt]     = 1.0f / g_rowsum[gz + r0];
            inv[2 * mt + 1] = 1.0f / g_rowsum[gz + r0 + 8];
        }
    }

#pragma unroll
    for (int mt = 0; mt < 4; mt++) {
        const long long r0 = m0 + wm * 64 + mt * 16 + g;
        float rs0 = 0.f, rs1 = 0.f;     // EPI_EXP_H row-sum partials
#pragma unroll
        for (int nt = 0; nt < 8; nt++) {
            const int col = n0 + wn * 64 + nt * 8 + t * 2;
            float v0 = acc[mt][nt][0], v1 = acc[mt][nt][1];
            float v2 = acc[mt][nt][2], v3 = acc[mt][nt][3];

            if (EPI == EPI_NORM) {
                const float i0 = inv[2 * mt], i1 = inv[2 * mt + 1];
                *(float2*)(Cf + r0 * N + col)       = make_float2(v0 * i0, v1 * i0);
                *(float2*)(Cf + (r0 + 8) * N + col) = make_float2(v2 * i1, v3 * i1);
            } else if (EPI == EPI_EXP_H) {
                float e0 = __expf(v0 * scale), e1 = __expf(v1 * scale);
                float e2 = __expf(v2 * scale), e3 = __expf(v3 * scale);
                *(__half2*)(Ch + r0 * N + col)       = __floats2half2_rn(e0, e1);
                *(__half2*)(Ch + (r0 + 8) * N + col) = __floats2half2_rn(e2, e3);
                rs0 += e0 + e1;
                rs1 += e2 + e3;
            } else {  // EPI_QKV
                const float2 bv = *(const float2*)(g_bias + col);
                const __half2 h01 = __floats2half2_rn(v0 + bv.x, v1 + bv.y);
                const __half2 h23 = __floats2half2_rn(v2 + bv.x, v3 + bv.y);
                const int mat = col >> 10;           // 0=q 1=k 2=v
                const int cl  = col & 1023;
                if (mat == 0) {
                    *(__half2*)(g_q + r0 * DIM + cl)       = h01;
                    *(__half2*)(g_q + (r0 + 8) * DIM + cl) = h23;
                } else if (mat == 1) {
                    *(__half2*)(g_k + r0 * DIM + cl)       = h01;
                    *(__half2*)(g_k + (r0 + 8) * DIM + cl) = h23;
                } else {
                    const long long bofs = (r0 >> 11) * (long long)DIM * SEQ;
                    const long long sq0 = r0 & 2047, sq1 = (r0 + 8) & 2047;
                    g_vt[bofs + (long long)(cl    ) * SEQ + sq0] = __low2half(h01);
                    g_vt[bofs + (long long)(cl + 1) * SEQ + sq0] = __high2half(h01);
                    g_vt[bofs + (long long)(cl    ) * SEQ + sq1] = __low2half(h23);
                    g_vt[bofs + (long long)(cl + 1) * SEQ + sq1] = __high2half(h23);
                }
            }
        }
        if (EPI == EPI_EXP_H) {
            rs0 += __shfl_xor_sync(0xffffffffu, rs0, 1);
            rs0 += __shfl_xor_sync(0xffffffffu, rs0, 2);
            rs1 += __shfl_xor_sync(0xffffffffu, rs1, 1);
            rs1 += __shfl_xor_sync(0xffffffffu, rs1, 2);
            if (t == 0) {
                atomicAdd(&g_rowsum[gz + r0],     rs0);
                atomicAdd(&g_rowsum[gz + r0 + 8], rs1);
            }
        }
    }
}

// ------------------------------ launch -------------------------------------
extern "C" void kernel_launch(void* const* d_in, const int* in_sizes, int n_in,
                              void* d_out, int out_size)
{
    (void)in_sizes; (void)n_in; (void)out_size;
    const float* x  = (const float*)d_in[0];
    const float* Wq = (const float*)d_in[1];
    const float* bq = (const float*)d_in[2];
    const float* Wk = (const float*)d_in[3];
    const float* bk = (const float*)d_in[4];
    const float* Wv = (const float*)d_in[5];
    const float* bv = (const float*)d_in[6];
    float* out = (float*)d_out;

    __half *xh, *wqkv, *q, *k, *vt, *p;
    cudaGetSymbolAddress((void**)&xh,   g_xh);
    cudaGetSymbolAddress((void**)&wqkv, g_wqkv);
    cudaGetSymbolAddress((void**)&q,    g_q);
    cudaGetSymbolAddress((void**)&k,    g_k);
    cudaGetSymbolAddress((void**)&vt,   g_vt);
    cudaGetSymbolAddress((void**)&p,    g_p);

    cudaFuncSetAttribute(gemm_f16<EPI_QKV>,   cudaFuncAttributeMaxDynamicSharedMemorySize, GEMM_SMEM);
    cudaFuncSetAttribute(gemm_f16<EPI_EXP_H>, cudaFuncAttributeMaxDynamicSharedMemorySize, GEMM_SMEM);
    cudaFuncSetAttribute(gemm_f16<EPI_NORM>,  cudaFuncAttributeMaxDynamicSharedMemorySize, GEMM_SMEM);

    // 1) prepass: round x + weights to fp16, pack biases, zero rowsums
    prepass_kernel<<<N4_ALL / 256, 256>>>(
        (const float4*)x, (const float4*)Wq, (const float4*)Wk, (const float4*)Wv,
        (const float4*)bq, (const float4*)bk, (const float4*)bv);

    // 2) fused QKV: [8192,1024] @ [3072,1024]^T -> g_q / g_k / g_vt
    {
        dim3 grid(3 * DIM / 128, BS_ / 128, 1);
        gemm_f16<EPI_QKV><<<grid, 128, GEMM_SMEM>>>(
            xh, wqkv, nullptr, DIM, 3 * DIM, 0, 0, 0, 1.0f);
    }

    // 3) P' = exp(QK^T / 32) -> fp16 g_p + row sums (sC in half units)
    {
        dim3 grid(SEQ / 128, SEQ / 128, BATCH);
        gemm_f16<EPI_EXP_H><<<grid, 128, GEMM_SMEM>>>(
            q, k, (float*)p, DIM, SEQ,
            (long long)SEQ * DIM, (long long)SEQ * DIM, (long long)SEQ * SEQ, 0.03125f);
    }

    // 4) out = (P' @ V) / rowsum  (V^T fp16 [DIM,SEQ] K-major), fp32 out
    {
        dim3 grid(DIM / 128, SEQ / 128, BATCH);
        gemm_f16<EPI_NORM><<<grid, 128, GEMM_SMEM>>>(
            p, vt, out, SEQ, DIM,
            (long long)SEQ * SEQ, (long long)DIM * SEQ, (long long)SEQ * DIM, 1.0f);
    }
}

// round 14
// speedup vs baseline: 1.0226x; 1.0135x over previous
#include <cuda_runtime.h>
#include <cuda_fp16.h>
#include <cstdint>

// ---------------------------------------------------------------------------
// SelfAttention B=4, S=2048, D=1024 fp32 — persistent fused mma.sync pipeline.
// R13 -> R14: ALL GEMM tiles (QKV proj, exp-scores, PV) run in ONE persistent
// kernel (2 CTAs/SM, all resident) with a dependency-tracked static tile
// scheduler -> no wave-quantization tails between phases. Mainloop identical
// to the 303us kernel (128x128 tile, BK=64, 3-stage interleaved cp.async).
// ---------------------------------------------------------------------------

#define BATCH 4
#define SEQ   2048
#define DIM   1024
#define BS_   (BATCH * SEQ)

__device__ __half g_xh  [BS_ * DIM];                 // rounded x (fp16)
__device__ __half g_wqkv[3 * DIM * DIM];             // rounded [Wq;Wk;Wv]
__device__ float  g_bias[3 * DIM];                   // [bq;bk;bv] fp32
__device__ __half g_q [BS_ * DIM];                   // Q fp16
__device__ __half g_k [BS_ * DIM];                   // K fp16
__device__ __half g_vt[BS_ * DIM];                   // V^T fp16 [B][D][S]
__device__ __half g_p [(size_t)BATCH * SEQ * SEQ];   // P' = exp(s/32) fp16
__device__ float  g_rowsum[BS_];                     // softmax denominators
// flags: [0,64) q-row ready (target 8) | [64,128) k-row (8)
//        [128,192) scores-row done (16) | [192,224) v (batch,dimtile) (16)
__device__ int    g_flags[224];

// work item counts
#define NW_QKV 1536
#define NW_S   1024
#define NW_PV  512
#define NW_ALL 3072

// ------------------------------ helpers -----------------------------------
__device__ __forceinline__ uint32_t smem_u32(const void* p) {
    uint32_t a;
    asm("{ .reg .u64 t; cvta.to.shared.u64 t, %1; cvt.u32.u64 %0, t; }"
        : "=r"(a) : "l"(p));
    return a;
}
__device__ __forceinline__ void cp16(uint32_t dst, const void* src) {
    asm volatile("cp.async.cg.shared.global [%0], [%1], 16;\n"
                 :: "r"(dst), "l"(src));
}
__device__ __forceinline__ void ldsm_x4(uint32_t* r, uint32_t a) {
    asm volatile("ldmatrix.sync.aligned.m8n8.x4.shared.b16 {%0,%1,%2,%3}, [%4];"
                 : "=r"(r[0]), "=r"(r[1]), "=r"(r[2]), "=r"(r[3]) : "r"(a));
}
__device__ __forceinline__ void mma_f16(float* c, const uint32_t* a, const uint32_t* b) {
    asm volatile(
        "mma.sync.aligned.m16n8k16.row.col.f32.f16.f16.f32 "
        "{%0,%1,%2,%3}, {%4,%5,%6,%7}, {%8,%9}, {%0,%1,%2,%3};"
        : "+f"(c[0]), "+f"(c[1]), "+f"(c[2]), "+f"(c[3])
        : "r"(a[0]), "r"(a[1]), "r"(a[2]), "r"(a[3]), "r"(b[0]), "r"(b[1]));
}
#define SW128(o) ((o) ^ (((o) >> 3) & 0x70))

// ------------------------------ fused prepass ------------------------------
#define N4_X   (BS_ * DIM / 4)
#define N4_W   (3 * DIM * DIM / 4)
#define N4_W1  (DIM * DIM / 4)
#define N4_B1  (DIM / 4)
#define N4_RS  (BS_ / 4)
#define N4_FL  56                               // 224 ints = 56 float4
#define N4_TOT (N4_X + N4_W + 3 * N4_B1 + N4_RS + N4_FL)

__global__ void __launch_bounds__(256) prepass_kernel(
    const float4* __restrict__ x,
    const float4* __restrict__ Wq, const float4* __restrict__ Wk,
    const float4* __restrict__ Wv,
    const float4* __restrict__ bq, const float4* __restrict__ bk,
    const float4* __restrict__ bv)
{
    int i = blockIdx.x * blockDim.x + threadIdx.x;
    if (i >= N4_TOT) return;
    if (i < N4_X) {
        float4 v = x[i];
        ((__half2*)g_xh)[2 * i]     = __floats2half2_rn(v.x, v.y);
        ((__half2*)g_xh)[2 * i + 1] = __floats2half2_rn(v.z, v.w);
    } else if (i < N4_X + N4_W) {
        int j = i - N4_X;
        float4 v = (j < N4_W1) ? Wq[j]
                 : (j < 2 * N4_W1) ? Wk[j - N4_W1] : Wv[j - 2 * N4_W1];
        ((__half2*)g_wqkv)[2 * j]     = __floats2half2_rn(v.x, v.y);
        ((__half2*)g_wqkv)[2 * j + 1] = __floats2half2_rn(v.z, v.w);
    } else if (i < N4_X + N4_W + 3 * N4_B1) {
        int j = i - N4_X - N4_W;
        float4 v = (j < N4_B1) ? bq[j]
                 : (j < 2 * N4_B1) ? bk[j - N4_B1] : bv[j - 2 * N4_B1];
        ((float4*)g_bias)[j] = v;
    } else if (i < N4_X + N4_W + 3 * N4_B1 + N4_RS) {
        int j = i - N4_X - N4_W - 3 * N4_B1;
        ((float4*)g_rowsum)[j] = make_float4(0.f, 0.f, 0.f, 0.f);
    } else {
        int j = i - N4_X - N4_W - 3 * N4_B1 - N4_RS;
        ((float4*)g_flags)[j] = make_float4(0.f, 0.f, 0.f, 0.f);
    }
}

// ------------------------------ persistent GEMM ----------------------------
#define A_TILE 16384
#define B_TILE 16384
#define STAGE  (A_TILE + B_TILE)
#define NSTAGE 3
#define GEMM_SMEM (NSTAGE * STAGE)   // 96 KB

__global__ void __launch_bounds__(128, 2) attn_persistent(
    const __half* __restrict__ xh, const __half* __restrict__ wqkv,
    __half* __restrict__ q, __half* __restrict__ k,
    __half* __restrict__ vt, __half* __restrict__ p,
    float* __restrict__ out, int nCta)
{
    extern __shared__ __align__(128) char smem[];
    const uint32_t base = smem_u32(smem);

    const int tid = threadIdx.x;
    const int wid = tid >> 5, lid = tid & 31;
    const int wm = wid & 1;
    const int wn = wid >> 1;

    // lane addressing (item-independent)
    const int a_row_l = ((lid >> 3) & 1) * 8 + (lid & 7);
    const int a_hi    = lid >> 4;
    uint32_t a_rb[4]; int a_rx[4];
#pragma unroll
    for (int mt = 0; mt < 4; mt++) {
        int fr = wm * 64 + mt * 16 + a_row_l;
        a_rb[mt] = fr * 128; a_rx[mt] = fr & 7;
    }
    const int b4_row = ((lid >> 4) << 3) + (lid & 7);
    const int b4_hi  = (lid >> 3) & 1;
    uint32_t b_rb[4]; int b_rx[4];
#pragma unroll
    for (int nt2 = 0; nt2 < 4; nt2++) {
        int fr = wn * 64 + nt2 * 16 + b4_row;
        b_rb[nt2] = fr * 128; b_rx[nt2] = fr & 7;
    }
    const int l_r = tid >> 3;
    const int l_c = tid & 7;
    const int g = lid >> 2, t = lid & 3;

    for (int w = blockIdx.x; w < NW_ALL; w += nCta) {
        // ---------------- decode work item ----------------
        int phase, m0e;          // m0e: epilogue row base (batch-local for S/PV)
        int n0, z = 0, Kd;
        const __half *Ab, *Bb;
        int flagIdx = -1;        // producer flag to bump (-1 = none)

        if (w < NW_QKV) {
            phase = 0;
            int mx = w / 24, nx = w - mx * 24;
            Ab = xh   + (long long)mx * 128 * DIM;
            Bb = wqkv + (long long)nx * 128 * DIM;
            Kd = DIM; m0e = mx * 128; n0 = nx * 128;
            flagIdx = (nx < 8) ? mx : (nx < 16) ? 64 + mx
                                    : 192 + (mx >> 4) * 8 + (nx - 16);
        } else if (w < NW_QKV + NW_S) {
            phase = 1;
            int w2 = w - NW_QKV;
            z = w2 >> 8; int r = w2 & 255; int my = r >> 4; int nx = r & 15;
            Ab = q + ((long long)z * SEQ + my * 128) * DIM;
            Bb = k + ((long long)z * SEQ + nx * 128) * DIM;
            Kd = DIM; m0e = my * 128; n0 = nx * 128;
            flagIdx = 128 + z * 16 + my;
            if (tid == 0) {   // wait for Q row-block + K row-block
                while (atomicAdd(&g_flags[z * 16 + my], 0) < 8) __nanosleep(128);
                while (atomicAdd(&g_flags[64 + z * 16 + nx], 0) < 8) __nanosleep(128);
            }
        } else {
            phase = 2;
            int w3 = w - (NW_QKV + NW_S);
            z = w3 >> 7; int r = w3 & 127; int my = r >> 3; int nx = r & 7;
            Ab = p  + (long long)z * SEQ * SEQ + (long long)my * 128 * SEQ;
            Bb = vt + (long long)z * DIM * SEQ + (long long)nx * 128 * SEQ;
            Kd = SEQ; m0e = my * 128; n0 = nx * 128;
            if (tid == 0) {   // wait for scores row-block + V dim-block
                while (atomicAdd(&g_flags[128 + z * 16 + my], 0) < 16) __nanosleep(128);
                while (atomicAdd(&g_flags[192 + z * 8 + nx], 0) < 16) __nanosleep(128);
            }
        }
        __syncthreads();   // deps ready + previous item's smem fully drained

        // ---------------- mainloop ----------------
        float acc[4][8][4];
#pragma unroll
        for (int mt = 0; mt < 4; mt++)
#pragma unroll
            for (int nt = 0; nt < 8; nt++)
#pragma unroll
                for (int r = 0; r < 4; r++) acc[mt][nt][r] = 0.f;

        auto load_tile = [&](int j, int b) {
            const uint32_t sa = base + b * STAGE;
            const uint32_t sb = sa + A_TILE;
            const __half* At = Ab + (long long)j * 64;
            const __half* Bt = Bb + (long long)j * 64;
#pragma unroll
            for (int tt = 0; tt < 8; tt++) {
                int r = l_r + tt * 16;
                cp16(sa + SW128(r * 128 + l_c * 16), At + (long long)r * Kd + l_c * 8);
            }
#pragma unroll
            for (int tt = 0; tt < 8; tt++) {
                int r = l_r + tt * 16;
                cp16(sb + SW128(r * 128 + l_c * 16), Bt + (long long)r * Kd + l_c * 8);
            }
            asm volatile("cp.async.commit_group;" ::: "memory");
        };

        const int T = Kd >> 6;
        load_tile(0, 0);
        load_tile(1, 1);

        int cb = 0, pb = 2;
        for (int i = 0; i < T; i++) {
            if (i < T - 1) asm volatile("cp.async.wait_group 1;" ::: "memory");
            else           asm volatile("cp.async.wait_group 0;" ::: "memory");
            __syncthreads();

            const bool pf = (i + 2 < T);
            const uint32_t sa = base + cb * STAGE;
            const uint32_t sb = sa + A_TILE;
            const uint32_t pa = base + pb * STAGE;
            const uint32_t pbb = pa + A_TILE;
            const __half* At = Ab + (long long)(i + 2) * 64;
            const __half* Bt = Bb + (long long)(i + 2) * 64;

#pragma unroll
            for (int s = 0; s < 4; s++) {
                uint32_t af[4][4], bf[8][2];
#pragma unroll
                for (int qq = 0; qq < 4; qq++) {
                    ldsm_x4(af[qq], sa + a_rb[qq] + ((((s << 1) | a_hi) ^ a_rx[qq]) << 4));
                    uint32_t r[4];
                    ldsm_x4(r, sb + b_rb[qq] + ((((s << 1) | b4_hi) ^ b_rx[qq]) << 4));
                    bf[2 * qq][0]     = r[0]; bf[2 * qq][1]     = r[1];
                    bf[2 * qq + 1][0] = r[2]; bf[2 * qq + 1][1] = r[3];
                }
                if (pf) {
                    int r0 = l_r + (2 * s) * 16, r1 = l_r + (2 * s + 1) * 16;
                    cp16(pa  + SW128(r0 * 128 + l_c * 16), At + (long long)r0 * Kd + l_c * 8);
                    cp16(pa  + SW128(r1 * 128 + l_c * 16), At + (long long)r1 * Kd + l_c * 8);
                    cp16(pbb + SW128(r0 * 128 + l_c * 16), Bt + (long long)r0 * Kd + l_c * 8);
                    cp16(pbb + SW128(r1 * 128 + l_c * 16), Bt + (long long)r1 * Kd + l_c * 8);
                }
#pragma unroll
                for (int mt = 0; mt < 4; mt++)
#pragma unroll
                    for (int nt = 0; nt < 8; nt++)
                        mma_f16(acc[mt][nt], af[mt], bf[nt]);
            }
            if (pf) asm volatile("cp.async.commit_group;" ::: "memory");
            cb = (cb == NSTAGE - 1) ? 0 : cb + 1;
            pb = (pb == NSTAGE - 1) ? 0 : pb + 1;
        }

        // ---------------- epilogue ----------------
        if (phase == 0) {           // QKV: +bias, round fp16, route
#pragma unroll
            for (int mt = 0; mt < 4; mt++) {
                const long long r0 = m0e + wm * 64 + mt * 16 + g;
#pragma unroll
                for (int nt = 0; nt < 8; nt++) {
                    const int col = n0 + wn * 64 + nt * 8 + t * 2;
                    const float2 bv = *(const float2*)(g_bias + col);
                    const __half2 h01 = __floats2half2_rn(acc[mt][nt][0] + bv.x,
                                                          acc[mt][nt][1] + bv.y);
                    const __half2 h23 = __floats2half2_rn(acc[mt][nt][2] + bv.x,
                                                          acc[mt][nt][3] + bv.y);
                    const int mat = col >> 10;
                    const int cl  = col & 1023;
                    if (mat == 0) {
                        *(__half2*)(q + r0 * DIM + cl)       = h01;
                        *(__half2*)(q + (r0 + 8) * DIM + cl) = h23;
                    } else if (mat == 1) {
                        *(__half2*)(k + r0 * DIM + cl)       = h01;
                        *(__half2*)(k + (r0 + 8) * DIM + cl) = h23;
                    } else {
                        const long long bofs = (r0 >> 11) * (long long)DIM * SEQ;
                        const long long sq0 = r0 & 2047, sq1 = (r0 + 8) & 2047;
                        vt[bofs + (long long)(cl    ) * SEQ + sq0] = __low2half(h01);
                        vt[bofs + (long long)(cl + 1) * SEQ + sq0] = __high2half(h01);
                        vt[bofs + (long long)(cl    ) * SEQ + sq1] = __low2half(h23);
                        vt[bofs + (long long)(cl + 1) * SEQ + sq1] = __high2half(h23);
                    }
                }
            }
        } else if (phase == 1) {    // scores: exp(acc/32) fp16 + rowsums
            __half* Ch = p + (long long)z * SEQ * SEQ;
            const int gz = z * SEQ;
#pragma unroll
            for (int mt = 0; mt < 4; mt++) {
                const long long r0 = m0e + wm * 64 + mt * 16 + g;
                float rs0 = 0.f, rs1 = 0.f;
#pragma unroll
                for (int nt = 0; nt < 8; nt++) {
                    const int col = n0 + wn * 64 + nt * 8 + t * 2;
                    float e0 = __expf(acc[mt][nt][0] * 0.03125f);
                    float e1 = __expf(acc[mt][nt][1] * 0.03125f);
                    float e2 = __expf(acc[mt][nt][2] * 0.03125f);
                    float e3 = __expf(acc[mt][nt][3] * 0.03125f);
                    *(__half2*)(Ch + r0 * SEQ + col)       = __floats2half2_rn(e0, e1);
                    *(__half2*)(Ch + (r0 + 8) * SEQ + col) = __floats2half2_rn(e2, e3);
                    rs0 += e0 + e1;
                    rs1 += e2 + e3;
                }
                rs0 += __shfl_xor_sync(0xffffffffu, rs0, 1);
                rs0 += __shfl_xor_sync(0xffffffffu, rs0, 2);
                rs1 += __shfl_xor_sync(0xffffffffu, rs1, 1);
                rs1 += __shfl_xor_sync(0xffffffffu, rs1, 2);
                if (t == 0) {
                    atomicAdd(&g_rowsum[gz + r0],     rs0);
                    atomicAdd(&g_rowsum[gz + r0 + 8], rs1);
                }
            }
        } else {                    // PV: normalize by rowsum, fp32 out
            float* Cf = out + (long long)z * SEQ * DIM;
            const int gz = z * SEQ;
#pragma unroll
            for (int mt = 0; mt < 4; mt++) {
                const long long r0 = m0e + wm * 64 + mt * 16 + g;
                const float i0 = 1.0f / g_rowsum[gz + r0];
                const float i1 = 1.0f / g_rowsum[gz + r0 + 8];
#pragma unroll
                for (int nt = 0; nt < 8; nt++) {
                    const int col = n0 + wn * 64 + nt * 8 + t * 2;
                    *(float2*)(Cf + r0 * DIM + col) =
                        make_float2(acc[mt][nt][0] * i0, acc[mt][nt][1] * i0);
                    *(float2*)(Cf + (r0 + 8) * DIM + col) =
                        make_float2(acc[mt][nt][2] * i1, acc[mt][nt][3] * i1);
                }
            }
        }

        // ---------------- publish ----------------
        if (flagIdx >= 0) {
            __threadfence();
            __syncthreads();
            if (tid == 0) atomicAdd(&g_flags[flagIdx], 1);
        }
    }
}

// ------------------------------ launch -------------------------------------
extern "C" void kernel_launch(void* const* d_in, const int* in_sizes, int n_in,
                              void* d_out, int out_size)
{
    (void)in_sizes; (void)n_in; (void)out_size;
    const float* x  = (const float*)d_in[0];
    const float* Wq = (const float*)d_in[1];
    const float* bq = (const float*)d_in[2];
    const float* Wk = (const float*)d_in[3];
    const float* bk = (const float*)d_in[4];
    const float* Wv = (const float*)d_in[5];
    const float* bv = (const float*)d_in[6];
    float* out = (float*)d_out;

    __half *xh, *wqkv, *q, *k, *vt, *p;
    cudaGetSymbolAddress((void**)&xh,   g_xh);
    cudaGetSymbolAddress((void**)&wqkv, g_wqkv);
    cudaGetSymbolAddress((void**)&q,    g_q);
    cudaGetSymbolAddress((void**)&k,    g_k);
    cudaGetSymbolAddress((void**)&vt,   g_vt);
    cudaGetSymbolAddress((void**)&p,    g_p);

    cudaFuncSetAttribute(attn_persistent,
                         cudaFuncAttributeMaxDynamicSharedMemorySize, GEMM_SMEM);

    int smCount = 148;
    cudaDeviceGetAttribute(&smCount, cudaDevAttrMultiProcessorCount, 0);
    const int nCta = 2 * smCount;   // all resident (launch_bounds(128,2))

    // 1) prepass: round inputs to fp16, pack biases, zero rowsums + flags
    prepass_kernel<<<(N4_TOT + 255) / 256, 256>>>(
        (const float4*)x, (const float4*)Wq, (const float4*)Wk, (const float4*)Wv,
        (const float4*)bq, (const float4*)bk, (const float4*)bv);

    // 2) persistent fused QKV -> exp-scores -> PV
    attn_persistent<<<nCta, 128, GEMM_SMEM>>>(xh, wqkv, q, k, vt, p, out, nCta);
}